// round 5
// baseline (speedup 1.0000x reference)
#include <cuda_runtime.h>

// GCN 2-layer, scatter-reassociated + normalization-reassociated.
//
// t[d]  = dinv[d] * ( dinv[d]*x[d] + sum_e ew * dinv[s]*x[s] )
// out[d]= dinv[d] * ( dinv[d]*hw[d] + sum_e ew * dinv[s]*hw[s] ) + b2
//
// Edge passes: exactly one random gather + one random reduction per edge
// (the algorithmic minimum given the deg -> dinv -> layer1 -> layer2 chain).
// R5: edge/deg kernels are persistent-shaped grid-stride loops (1184 blocks,
// 8/SM guaranteed residency) so consecutive iterations give per-thread MLP on
// the random accesses and the 12500-block wave overhead disappears.

#define NMAX 131072
#define TPB 256
#define EDGE_BLOCKS 1184   // 148 SMs * 8 blocks (sm_100a); grid-stride correct anyway

__device__ float  g_dinv[NMAX];   // deg during accumulation, then dinv
__device__ float2 g_xd[NMAX];     // dinv[i] * x[i]          (gather source)
__device__ float2 g_u[NMAX];      // scatter target layer 1  (init = xd)
__device__ float  g_hws[NMAX];    // dinv[i] * hw[i]         (gather source)

__device__ __forceinline__ void pdl_prologue() {
    cudaGridDependencySynchronize();            // wait for predecessor's writes
    cudaTriggerProgrammaticLaunchCompletion();  // let successor prelaunch early
}

// ---- kernel 0: deg init = 1.0 (self-loop weight) ---------------------------
__global__ void __launch_bounds__(TPB) k_init(int n) {
    pdl_prologue();
    int i = blockIdx.x * blockDim.x + threadIdx.x;
    if (i < n) g_dinv[i] = 1.0f;
}

// ---- kernel 1: deg[dst] += ew  (grid-stride) --------------------------------
__global__ void __launch_bounds__(TPB, 8) k_deg(const int* __restrict__ dst,
                                                const float* __restrict__ ew, int E) {
    pdl_prologue();
    int stride = gridDim.x * blockDim.x;
    #pragma unroll 4
    for (int e = blockIdx.x * blockDim.x + threadIdx.x; e < E; e += stride)
        atomicAdd(&g_dinv[dst[e]], ew[e]);
}

// ---- kernel 2: dinv = rsqrt(deg); xd = dinv*x; u init = xd (self loop) -----
__global__ void __launch_bounds__(TPB) k_node1(const float2* __restrict__ x, int n) {
    pdl_prologue();
    int i = blockIdx.x * blockDim.x + threadIdx.x;
    if (i >= n) return;
    float d = g_dinv[i];
    float r = (d > 0.0f) ? rsqrtf(d) : 0.0f;
    g_dinv[i] = r;
    float2 xv = x[i];
    float2 xd = make_float2(r * xv.x, r * xv.y);
    g_xd[i] = xd;
    g_u[i]  = xd;   // self-loop term (outer dinv applied later)
}

// ---- kernel 3: layer-1 edge scatter: u[d] += ew * xd[s]  (grid-stride) ------
__global__ void __launch_bounds__(TPB, 8) k_edge1(const int* __restrict__ src,
                                                  const int* __restrict__ dst,
                                                  const float* __restrict__ ew, int E) {
    pdl_prologue();
    int stride = gridDim.x * blockDim.x;
    #pragma unroll 4
    for (int e = blockIdx.x * blockDim.x + threadIdx.x; e < E; e += stride) {
        int s = src[e];
        int d = dst[e];
        float w = ew[e];
        float2 xd = __ldg(&g_xd[s]);
        float a = w * xd.x;
        float b = w * xd.y;
        asm volatile("red.global.add.v2.f32 [%0], {%1, %2};"
                     :: "l"(&g_u[d]), "f"(a), "f"(b) : "memory");
    }
}

// ---- kernel 4: t = dinv*u; MLP; hws = dinv*hw; out init = hws ---------------
__global__ void __launch_bounds__(TPB) k_node2(const float* __restrict__ W1,
                                               const float* __restrict__ b1,
                                               const float* __restrict__ W2,
                                               float* __restrict__ out, int n) {
    pdl_prologue();
    int i = blockIdx.x * blockDim.x + threadIdx.x;
    if (i >= n) return;
    float r = g_dinv[i];
    float2 u = g_u[i];
    float tx = r * u.x;
    float ty = r * u.y;
    float acc = 0.0f;
#pragma unroll
    for (int k = 0; k < 16; k++) {
        float h = fmaf(tx, __ldg(&W1[k]),
                  fmaf(ty, __ldg(&W1[16 + k]), __ldg(&b1[k])));
        h = fmaxf(h, 0.0f);
        acc = fmaf(h, __ldg(&W2[k]), acc);
    }
    float hws = r * acc;
    g_hws[i] = hws;
    out[i]   = hws;   // self-loop init (outer dinv + b2 applied in k_node3)
}

// ---- kernel 5: layer-2 edge scatter: out[d] += ew * hws[s]  (grid-stride) ---
__global__ void __launch_bounds__(TPB, 8) k_edge2(const int* __restrict__ src,
                                                  const int* __restrict__ dst,
                                                  const float* __restrict__ ew,
                                                  float* __restrict__ out, int E) {
    pdl_prologue();
    int stride = gridDim.x * blockDim.x;
    #pragma unroll 4
    for (int e = blockIdx.x * blockDim.x + threadIdx.x; e < E; e += stride) {
        int s = src[e];
        int d = dst[e];
        atomicAdd(&out[d], ew[e] * __ldg(&g_hws[s]));
    }
}

// ---- kernel 6: out = dinv*out + b2 ------------------------------------------
__global__ void __launch_bounds__(TPB) k_node3(const float* __restrict__ b2,
                                               float* __restrict__ out, int n) {
    pdl_prologue();
    int i = blockIdx.x * blockDim.x + threadIdx.x;
    if (i >= n) return;
    out[i] = fmaf(g_dinv[i], out[i], __ldg(&b2[0]));
}

// ---- host: launch all kernels with programmatic stream serialization --------
template <typename F, typename... Args>
static void launch_pdl(F kernel, int nblocks, Args... args) {
    cudaLaunchConfig_t cfg = {};
    cfg.gridDim  = dim3((unsigned)nblocks, 1, 1);
    cfg.blockDim = dim3(TPB, 1, 1);
    cfg.dynamicSmemBytes = 0;
    cfg.stream = 0;
    cudaLaunchAttribute attr[1];
    attr[0].id = cudaLaunchAttributeProgrammaticStreamSerialization;
    attr[0].val.programmaticStreamSerializationAllowed = 1;
    cfg.attrs = attr;
    cfg.numAttrs = 1;
    cudaLaunchKernelEx(&cfg, kernel, args...);
}

extern "C" void kernel_launch(void* const* d_in, const int* in_sizes, int n_in,
                              void* d_out, int out_size) {
    const float* x  = (const float*)d_in[0];   // [N, 2]
    const int*   ei = (const int*)d_in[1];     // [2, E]
    const float* ew = (const float*)d_in[2];   // [E]
    const float* W1 = (const float*)d_in[3];   // [2, 16]
    const float* b1 = (const float*)d_in[4];   // [16]
    const float* W2 = (const float*)d_in[5];   // [16, 1]
    const float* b2 = (const float*)d_in[6];   // [1]
    float* out = (float*)d_out;                // [N, 1]

    int n = in_sizes[0] / 2;
    int E = in_sizes[2];
    const int* src = ei;
    const int* dst = ei + E;

    int nb_n = (n + TPB - 1) / TPB;

    launch_pdl(k_init,  nb_n, n);
    launch_pdl(k_deg,   EDGE_BLOCKS, dst, ew, E);
    launch_pdl(k_node1, nb_n, (const float2*)x, n);
    launch_pdl(k_edge1, EDGE_BLOCKS, src, dst, ew, E);
    launch_pdl(k_node2, nb_n, W1, b1, W2, out, n);
    launch_pdl(k_edge2, EDGE_BLOCKS, src, dst, ew, out, E);
    launch_pdl(k_node3, nb_n, b2, out, n);
}

// round 6
// speedup vs baseline: 1.1736x; 1.1736x over previous
#include <cuda_runtime.h>

// GCN 2-layer, scatter-reassociated + normalization-reassociated.
//
// t[d]  = dinv[d] * ( dinv[d]*x[d] + sum_e ew * dinv[s]*x[s] )
// out[d]= dinv[d] * ( dinv[d]*hw[d] + sum_e ew * dinv[s]*hw[s] ) + b2
//
// Proven shape (R4): 1 edge/thread flat grids, TPB=256, PDL between kernels.
// R3/R5 showed any reduction in warp count (vectorize or grid-stride) starves
// the latency-bound random-access pipeline.
//
// R6: k_init eliminated. k_deg accumulates into g_deg (zero-initialized device
// global); k_node1 computes deg = g_deg[i] + 1.0 (self-loop) and resets
// g_deg[i] = 0 for the next graph replay — deterministic per call.

#define NMAX 131072
#define TPB 256

__device__ float  g_deg[NMAX];    // edge-weight sums; zeroed by k_node1 each call
__device__ float  g_dinv[NMAX];   // rsqrt(deg)
__device__ float2 g_xd[NMAX];     // dinv[i] * x[i]          (gather source)
__device__ float2 g_u[NMAX];      // scatter target layer 1  (init = xd)
__device__ float  g_hws[NMAX];    // dinv[i] * hw[i]         (gather source)

__device__ __forceinline__ void pdl_prologue() {
    cudaGridDependencySynchronize();            // wait for predecessor's writes
    cudaTriggerProgrammaticLaunchCompletion();  // let successor prelaunch early
}

// ---- kernel 1: deg[dst] += ew ----------------------------------------------
__global__ void __launch_bounds__(TPB) k_deg(const int* __restrict__ dst,
                                             const float* __restrict__ ew, int E) {
    pdl_prologue();
    int e = blockIdx.x * blockDim.x + threadIdx.x;
    if (e < E) atomicAdd(&g_deg[dst[e]], ew[e]);
}

// ---- kernel 2: dinv = rsqrt(deg+1); reset deg; xd = dinv*x; u init = xd ----
__global__ void __launch_bounds__(TPB) k_node1(const float2* __restrict__ x, int n) {
    pdl_prologue();
    int i = blockIdx.x * blockDim.x + threadIdx.x;
    if (i >= n) return;
    float d = g_deg[i] + 1.0f;      // +1: self-loop weight; always > 0
    g_deg[i] = 0.0f;                // reset for next graph replay
    float r = rsqrtf(d);
    g_dinv[i] = r;
    float2 xv = x[i];
    float2 xd = make_float2(r * xv.x, r * xv.y);
    g_xd[i] = xd;
    g_u[i]  = xd;   // self-loop term (outer dinv applied later)
}

// ---- kernel 3: layer-1 edge scatter: u[d] += ew * xd[s] ---------------------
__global__ void __launch_bounds__(TPB) k_edge1(const int* __restrict__ src,
                                               const int* __restrict__ dst,
                                               const float* __restrict__ ew, int E) {
    pdl_prologue();
    int e = blockIdx.x * blockDim.x + threadIdx.x;
    if (e >= E) return;
    int s = src[e];
    int d = dst[e];
    float w = ew[e];
    float2 xd = __ldg(&g_xd[s]);
    float a = w * xd.x;
    float b = w * xd.y;
    asm volatile("red.global.add.v2.f32 [%0], {%1, %2};"
                 :: "l"(&g_u[d]), "f"(a), "f"(b) : "memory");
}

// ---- kernel 4: t = dinv*u; MLP; hws = dinv*hw; out init = hws ---------------
__global__ void __launch_bounds__(TPB) k_node2(const float* __restrict__ W1,
                                               const float* __restrict__ b1,
                                               const float* __restrict__ W2,
                                               float* __restrict__ out, int n) {
    pdl_prologue();
    int i = blockIdx.x * blockDim.x + threadIdx.x;
    if (i >= n) return;
    float r = g_dinv[i];
    float2 u = g_u[i];
    float tx = r * u.x;
    float ty = r * u.y;
    float acc = 0.0f;
#pragma unroll
    for (int k = 0; k < 16; k++) {
        float h = fmaf(tx, __ldg(&W1[k]),
                  fmaf(ty, __ldg(&W1[16 + k]), __ldg(&b1[k])));
        h = fmaxf(h, 0.0f);
        acc = fmaf(h, __ldg(&W2[k]), acc);
    }
    float hws = r * acc;
    g_hws[i] = hws;
    out[i]   = hws;   // self-loop init (outer dinv + b2 applied in k_node3)
}

// ---- kernel 5: layer-2 edge scatter: out[d] += ew * hws[s] ------------------
__global__ void __launch_bounds__(TPB) k_edge2(const int* __restrict__ src,
                                               const int* __restrict__ dst,
                                               const float* __restrict__ ew,
                                               float* __restrict__ out, int E) {
    pdl_prologue();
    int e = blockIdx.x * blockDim.x + threadIdx.x;
    if (e >= E) return;
    int s = src[e];
    int d = dst[e];
    atomicAdd(&out[d], ew[e] * __ldg(&g_hws[s]));
}

// ---- kernel 6: out = dinv*out + b2 ------------------------------------------
__global__ void __launch_bounds__(TPB) k_node3(const float* __restrict__ b2,
                                               float* __restrict__ out, int n) {
    pdl_prologue();
    int i = blockIdx.x * blockDim.x + threadIdx.x;
    if (i >= n) return;
    out[i] = fmaf(g_dinv[i], out[i], __ldg(&b2[0]));
}

// ---- host: launch all kernels with programmatic stream serialization --------
template <typename F, typename... Args>
static void launch_pdl(F kernel, int nblocks, Args... args) {
    cudaLaunchConfig_t cfg = {};
    cfg.gridDim  = dim3((unsigned)nblocks, 1, 1);
    cfg.blockDim = dim3(TPB, 1, 1);
    cfg.dynamicSmemBytes = 0;
    cfg.stream = 0;
    cudaLaunchAttribute attr[1];
    attr[0].id = cudaLaunchAttributeProgrammaticStreamSerialization;
    attr[0].val.programmaticStreamSerializationAllowed = 1;
    cfg.attrs = attr;
    cfg.numAttrs = 1;
    cudaLaunchKernelEx(&cfg, kernel, args...);
}

extern "C" void kernel_launch(void* const* d_in, const int* in_sizes, int n_in,
                              void* d_out, int out_size) {
    const float* x  = (const float*)d_in[0];   // [N, 2]
    const int*   ei = (const int*)d_in[1];     // [2, E]
    const float* ew = (const float*)d_in[2];   // [E]
    const float* W1 = (const float*)d_in[3];   // [2, 16]
    const float* b1 = (const float*)d_in[4];   // [16]
    const float* W2 = (const float*)d_in[5];   // [16, 1]
    const float* b2 = (const float*)d_in[6];   // [1]
    float* out = (float*)d_out;                // [N, 1]

    int n = in_sizes[0] / 2;
    int E = in_sizes[2];
    const int* src = ei;
    const int* dst = ei + E;

    int nb_n = (n + TPB - 1) / TPB;
    int nb_e = (E + TPB - 1) / TPB;

    launch_pdl(k_deg,   nb_e, dst, ew, E);
    launch_pdl(k_node1, nb_n, (const float2*)x, n);
    launch_pdl(k_edge1, nb_e, src, dst, ew, E);
    launch_pdl(k_node2, nb_n, W1, b1, W2, out, n);
    launch_pdl(k_edge2, nb_e, src, dst, ew, out, E);
    launch_pdl(k_node3, nb_n, b2, out, n);
}